// round 1
// baseline (speedup 1.0000x reference)
#include <cuda_runtime.h>
#include <cuda_bf16.h>
#include <cstdint>

// ---------------------------------------------------------------------------
// WindowedSelfAttention3D fused kernel.
// x:(2,128,64,64,64) f32. ws=4 -> 64 tokens/window, 8192 windows, heads=4, hd=32.
// One CTA (256 thr) per window. All GEMMs via mma.sync m16n8k16 bf16, fp32 acc.
// Conv done with hi/lo split of both y and conv_w for precision.
// ---------------------------------------------------------------------------

#define SMEM_BYTES 143872

// byte offsets into dynamic smem
#define OFF_XF    0        // float  [128][68]   (x window, channel-major)
#define OFF_ABUF  34816    // bf16   [64][136]   (xn, later o)
#define OFF_QS    52224    // bf16   [64][136]   (q, later y_hi)
#define OFF_KS    69632    // bf16   [64][136]   (k, later y_lo)
#define OFF_VT    87040    // bf16   [128][72]   (v transposed: [c][t])
#define OFF_WBUF  105472   // bf16   [128][136]  (weight stage / final f32 out [128][68])
#define OFF_BIAS  140288   // float  [896]: ln_g,ln_b,in_b(384),out_b,conv_b

__device__ __align__(16) __nv_bfloat16 g_win[384 * 128];
__device__ __align__(16) __nv_bfloat16 g_wout[128 * 128];
__device__ __align__(16) __nv_bfloat16 g_wc_hi[128 * 128];
__device__ __align__(16) __nv_bfloat16 g_wc_lo[128 * 128];

__global__ void convert_weights_kernel(const float* __restrict__ win,
                                       const float* __restrict__ wout,
                                       const float* __restrict__ wc) {
    int i = blockIdx.x * blockDim.x + threadIdx.x;
    if (i < 384 * 128) g_win[i] = __float2bfloat16(win[i]);
    if (i < 128 * 128) {
        g_wout[i] = __float2bfloat16(wout[i]);
        float f = wc[i];
        __nv_bfloat16 h = __float2bfloat16(f);
        g_wc_hi[i] = h;
        g_wc_lo[i] = __float2bfloat16(f - __bfloat162float(h));
    }
}

__device__ __forceinline__ void mma16816(float acc[4], uint32_t a0, uint32_t a1,
                                         uint32_t a2, uint32_t a3,
                                         uint32_t b0, uint32_t b1) {
    asm volatile(
        "mma.sync.aligned.m16n8k16.row.col.f32.bf16.bf16.f32 "
        "{%0,%1,%2,%3},{%4,%5,%6,%7},{%8,%9},{%0,%1,%2,%3};\n"
        : "+f"(acc[0]), "+f"(acc[1]), "+f"(acc[2]), "+f"(acc[3])
        : "r"(a0), "r"(a1), "r"(a2), "r"(a3), "r"(b0), "r"(b1));
}

// pack two floats -> bf16x2, lo at low 16 bits
__device__ __forceinline__ uint32_t packbf(float lo, float hi) {
    uint32_t r;
    asm("cvt.rn.bf16x2.f32 %0, %1, %2;" : "=r"(r) : "f"(hi), "f"(lo));
    return r;
}

// D[64][128] += A[64][128] (bf16, stride 136) @ W[128][128]^T (bf16, stride 136)
// warp tile: rows m0..m0+15, cols nbase..nbase+63 (8 n-tiles)
__device__ __forceinline__ void gemm_64_128(const __nv_bfloat16* __restrict__ A,
                                            const __nv_bfloat16* __restrict__ W,
                                            float acc[8][4], int m0, int nbase,
                                            int g, int q2) {
#pragma unroll
    for (int ks = 0; ks < 8; ks++) {
        int k0 = ks * 16;
        const __nv_bfloat16* Ar = A + (m0 + g) * 136 + k0 + q2;
        uint32_t a0 = *(const uint32_t*)(Ar);
        uint32_t a1 = *(const uint32_t*)(Ar + 8 * 136);
        uint32_t a2 = *(const uint32_t*)(Ar + 8);
        uint32_t a3 = *(const uint32_t*)(Ar + 8 * 136 + 8);
#pragma unroll
        for (int nt = 0; nt < 8; nt++) {
            const __nv_bfloat16* Br = W + (nbase + nt * 8 + g) * 136 + k0 + q2;
            mma16816(acc[nt], a0, a1, a2, a3,
                     *(const uint32_t*)(Br), *(const uint32_t*)(Br + 8));
        }
    }
}

// stage 128x128 bf16 weight block (row-major, K contiguous) into smem stride 136
__device__ __forceinline__ void load_w(const __nv_bfloat16* __restrict__ src,
                                       __nv_bfloat16* __restrict__ wbuf, int tid) {
#pragma unroll
    for (int it = 0; it < 8; it++) {
        int idx = it * 256 + tid;   // 2048 x uint4
        int row = idx >> 4;
        int cq = idx & 15;
        *(uint4*)(wbuf + row * 136 + cq * 8) =
            *(const uint4*)(src + row * 128 + cq * 8);
    }
}

__global__ void __launch_bounds__(256, 1)
fused_wsa3d_kernel(const float* __restrict__ x,
                   const float* __restrict__ ln_g, const float* __restrict__ ln_b,
                   const float* __restrict__ in_b, const float* __restrict__ out_b,
                   const float* __restrict__ conv_b,
                   float* __restrict__ out) {
    extern __shared__ char sm[];
    float* xf = (float*)(sm + OFF_XF);                          // [128][68]
    __nv_bfloat16* abuf = (__nv_bfloat16*)(sm + OFF_ABUF);      // [64][136]
    __nv_bfloat16* qs = (__nv_bfloat16*)(sm + OFF_QS);          // [64][136]
    __nv_bfloat16* ks_ = (__nv_bfloat16*)(sm + OFF_KS);         // [64][136]
    __nv_bfloat16* vT = (__nv_bfloat16*)(sm + OFF_VT);          // [128][72]
    __nv_bfloat16* wbuf = (__nv_bfloat16*)(sm + OFF_WBUF);      // [128][136]
    float* bias = (float*)(sm + OFF_BIAS);                      // [896]

    const int tid = threadIdx.x;
    const int warp = tid >> 5, lane = tid & 31;
    const int g = lane >> 2, q2 = (lane & 3) * 2;
    const int m0 = (warp & 3) * 16;
    const int nbase = (warp >> 2) * 64;

    // window coords
    const int widx = blockIdx.x;
    const int b = widx >> 12;
    const int r3 = widx & 4095;
    const int d0 = (r3 >> 8) * 4;
    const int h0 = ((r3 >> 4) & 15) * 4;
    const int w0 = (r3 & 15) * 4;
    const float* xb = x + (size_t)b * 128 * 262144;

    // biases / ln params into smem
    for (int i = tid; i < 896; i += 256) {
        float v;
        if (i < 128)        v = ln_g[i];
        else if (i < 256)   v = ln_b[i - 128];
        else if (i < 640)   v = in_b[i - 256];
        else if (i < 768)   v = out_b[i - 640];
        else                v = conv_b[i - 768];
        bias[i] = v;
    }

    // ---- load x window -> xf [c][t], t = dd*16 + hh*4 + ww ----
#pragma unroll
    for (int it = 0; it < 8; it++) {
        int idx = it * 256 + tid;        // 2048 float4s
        int c = idx >> 4;
        int row = idx & 15;              // (dd,hh)
        int dd = row >> 2, hh = row & 3;
        float4 v = *(const float4*)(xb + (size_t)c * 262144 +
                                    (size_t)(d0 + dd) * 4096 + (h0 + hh) * 64 + w0);
        *(float4*)(xf + c * 68 + row * 4) = v;
    }
    __syncthreads();

    // ---- LayerNorm over channels: 4 threads per token ----
    {
        int t = tid >> 2, j = tid & 3;
        float s = 0.f, s2 = 0.f;
#pragma unroll
        for (int i = 0; i < 32; i++) {
            float v = xf[(j + 4 * i) * 68 + t];
            s += v; s2 += v * v;
        }
        s  += __shfl_xor_sync(0xffffffffu, s, 1);
        s  += __shfl_xor_sync(0xffffffffu, s, 2);
        s2 += __shfl_xor_sync(0xffffffffu, s2, 1);
        s2 += __shfl_xor_sync(0xffffffffu, s2, 2);
        float mu = s * (1.f / 128.f);
        float var = s2 * (1.f / 128.f) - mu * mu;
        float rstd = rsqrtf(var + 1e-5f);
#pragma unroll
        for (int i = 0; i < 32; i++) {
            int c = j + 4 * i;
            float v = (xf[c * 68 + t] - mu) * rstd * bias[c] + bias[128 + c];
            abuf[t * 136 + c] = __float2bfloat16(v);
        }
    }
    __syncthreads();

    // ---- QKV projection: 3 chunks of 128 out-dims ----
#pragma unroll 1
    for (int chunk = 0; chunk < 3; chunk++) {
        load_w(g_win + chunk * 128 * 128, wbuf, tid);
        __syncthreads();
        float acc[8][4];
#pragma unroll
        for (int nt = 0; nt < 8; nt++)
#pragma unroll
            for (int i = 0; i < 4; i++) acc[nt][i] = 0.f;
        gemm_64_128(abuf, wbuf, acc, m0, nbase, g, q2);
#pragma unroll
        for (int nt = 0; nt < 8; nt++) {
            int col = nbase + nt * 8 + q2;
            float b0v = bias[256 + chunk * 128 + col];
            float b1v = bias[256 + chunk * 128 + col + 1];
            float v0 = acc[nt][0] + b0v, v1 = acc[nt][1] + b1v;
            float v2 = acc[nt][2] + b0v, v3 = acc[nt][3] + b1v;
            int t0 = m0 + g, t1 = m0 + 8 + g;
            if (chunk == 0) {
                *(uint32_t*)(qs + t0 * 136 + col) = packbf(v0, v1);
                *(uint32_t*)(qs + t1 * 136 + col) = packbf(v2, v3);
            } else if (chunk == 1) {
                *(uint32_t*)(ks_ + t0 * 136 + col) = packbf(v0, v1);
                *(uint32_t*)(ks_ + t1 * 136 + col) = packbf(v2, v3);
            } else {
                vT[col * 72 + t0]       = __float2bfloat16(v0);
                vT[(col + 1) * 72 + t0] = __float2bfloat16(v1);
                vT[col * 72 + t1]       = __float2bfloat16(v2);
                vT[(col + 1) * 72 + t1] = __float2bfloat16(v3);
            }
        }
        __syncthreads();
    }

    // ---- Attention: warp -> (head = warp/2, row-half = warp%2) ----
    {
        const int head = warp >> 1;
        const int am0 = (warp & 1) * 32;
        const int kbase = head * 32;
        float P[2][8][4];
#pragma unroll
        for (int mt = 0; mt < 2; mt++)
#pragma unroll
            for (int nt = 0; nt < 8; nt++)
#pragma unroll
                for (int i = 0; i < 4; i++) P[mt][nt][i] = 0.f;

#pragma unroll
        for (int mt = 0; mt < 2; mt++) {
#pragma unroll
            for (int ks2 = 0; ks2 < 2; ks2++) {
                int k0 = kbase + ks2 * 16;
                const __nv_bfloat16* Ar = qs + (am0 + mt * 16 + g) * 136 + k0 + q2;
                uint32_t a0 = *(const uint32_t*)(Ar);
                uint32_t a1 = *(const uint32_t*)(Ar + 8 * 136);
                uint32_t a2 = *(const uint32_t*)(Ar + 8);
                uint32_t a3 = *(const uint32_t*)(Ar + 8 * 136 + 8);
#pragma unroll
                for (int nt = 0; nt < 8; nt++) {
                    const __nv_bfloat16* Br = ks_ + (nt * 8 + g) * 136 + k0 + q2;
                    mma16816(P[mt][nt], a0, a1, a2, a3,
                             *(const uint32_t*)(Br), *(const uint32_t*)(Br + 8));
                }
            }
        }

        const float scale = 0.17677669529663687f;  // 1/sqrt(32)
        float accO[2][4][4];
#pragma unroll
        for (int mt = 0; mt < 2; mt++)
#pragma unroll
            for (int nt = 0; nt < 4; nt++)
#pragma unroll
                for (int i = 0; i < 4; i++) accO[mt][nt][i] = 0.f;

#pragma unroll
        for (int mt = 0; mt < 2; mt++) {
            float mA = -1e30f, mB = -1e30f;
#pragma unroll
            for (int nt = 0; nt < 8; nt++) {
                mA = fmaxf(mA, fmaxf(P[mt][nt][0], P[mt][nt][1]));
                mB = fmaxf(mB, fmaxf(P[mt][nt][2], P[mt][nt][3]));
            }
            mA = fmaxf(mA, __shfl_xor_sync(0xffffffffu, mA, 1));
            mA = fmaxf(mA, __shfl_xor_sync(0xffffffffu, mA, 2));
            mB = fmaxf(mB, __shfl_xor_sync(0xffffffffu, mB, 1));
            mB = fmaxf(mB, __shfl_xor_sync(0xffffffffu, mB, 2));
            float sA = 0.f, sB = 0.f;
#pragma unroll
            for (int nt = 0; nt < 8; nt++) {
                float e0 = __expf((P[mt][nt][0] - mA) * scale);
                float e1 = __expf((P[mt][nt][1] - mA) * scale);
                float e2 = __expf((P[mt][nt][2] - mB) * scale);
                float e3 = __expf((P[mt][nt][3] - mB) * scale);
                P[mt][nt][0] = e0; P[mt][nt][1] = e1;
                P[mt][nt][2] = e2; P[mt][nt][3] = e3;
                sA += e0 + e1; sB += e2 + e3;
            }
            sA += __shfl_xor_sync(0xffffffffu, sA, 1);
            sA += __shfl_xor_sync(0xffffffffu, sA, 2);
            sB += __shfl_xor_sync(0xffffffffu, sB, 1);
            sB += __shfl_xor_sync(0xffffffffu, sB, 2);
            float iA = 1.f / sA, iB = 1.f / sB;

            // P @ V : re-pack score D-frags into A-frags in registers
#pragma unroll
            for (int ks = 0; ks < 4; ks++) {
                uint32_t a0 = packbf(P[mt][2 * ks][0] * iA, P[mt][2 * ks][1] * iA);
                uint32_t a1 = packbf(P[mt][2 * ks][2] * iB, P[mt][2 * ks][3] * iB);
                uint32_t a2 = packbf(P[mt][2 * ks + 1][0] * iA, P[mt][2 * ks + 1][1] * iA);
                uint32_t a3 = packbf(P[mt][2 * ks + 1][2] * iB, P[mt][2 * ks + 1][3] * iB);
#pragma unroll
                for (int nt = 0; nt < 4; nt++) {
                    const __nv_bfloat16* Br = vT + (kbase + nt * 8 + g) * 72 + ks * 16 + q2;
                    mma16816(accO[mt][nt], a0, a1, a2, a3,
                             *(const uint32_t*)(Br), *(const uint32_t*)(Br + 8));
                }
            }
        }
        // store o into abuf (xn dead)
#pragma unroll
        for (int mt = 0; mt < 2; mt++)
#pragma unroll
            for (int nt = 0; nt < 4; nt++) {
                int cc = kbase + nt * 8 + q2;
                int t0 = am0 + mt * 16 + g;
                *(uint32_t*)(abuf + t0 * 136 + cc) = packbf(accO[mt][nt][0], accO[mt][nt][1]);
                *(uint32_t*)(abuf + (t0 + 8) * 136 + cc) = packbf(accO[mt][nt][2], accO[mt][nt][3]);
            }
    }
    __syncthreads();

    // ---- out_proj + residual -> y, split hi/lo into qs/ks_ ----
    load_w(g_wout, wbuf, tid);
    __syncthreads();
    {
        float acc[8][4];
#pragma unroll
        for (int nt = 0; nt < 8; nt++)
#pragma unroll
            for (int i = 0; i < 4; i++) acc[nt][i] = 0.f;
        gemm_64_128(abuf, wbuf, acc, m0, nbase, g, q2);
#pragma unroll
        for (int nt = 0; nt < 8; nt++) {
            int cc = nbase + nt * 8 + q2;
            int t0 = m0 + g, t1 = m0 + 8 + g;
            float y00 = acc[nt][0] + bias[640 + cc]     + xf[cc * 68 + t0];
            float y01 = acc[nt][1] + bias[640 + cc + 1] + xf[(cc + 1) * 68 + t0];
            float y10 = acc[nt][2] + bias[640 + cc]     + xf[cc * 68 + t1];
            float y11 = acc[nt][3] + bias[640 + cc + 1] + xf[(cc + 1) * 68 + t1];
            float h00 = __bfloat162float(__float2bfloat16(y00));
            float h01 = __bfloat162float(__float2bfloat16(y01));
            float h10 = __bfloat162float(__float2bfloat16(y10));
            float h11 = __bfloat162float(__float2bfloat16(y11));
            *(uint32_t*)(qs + t0 * 136 + cc) = packbf(y00, y01);
            *(uint32_t*)(qs + t1 * 136 + cc) = packbf(y10, y11);
            *(uint32_t*)(ks_ + t0 * 136 + cc) = packbf(y00 - h00, y01 - h01);
            *(uint32_t*)(ks_ + t1 * 136 + cc) = packbf(y10 - h10, y11 - h11);
        }
    }
    __syncthreads();

    // ---- conv: acc = y_hi@Wc_hi + y_lo@Wc_hi + y_hi@Wc_lo ----
    {
        float acc[8][4];
#pragma unroll
        for (int nt = 0; nt < 8; nt++)
#pragma unroll
            for (int i = 0; i < 4; i++) acc[nt][i] = 0.f;
        load_w(g_wc_hi, wbuf, tid);
        __syncthreads();
        gemm_64_128(qs, wbuf, acc, m0, nbase, g, q2);
        gemm_64_128(ks_, wbuf, acc, m0, nbase, g, q2);
        __syncthreads();
        load_w(g_wc_lo, wbuf, tid);
        __syncthreads();
        gemm_64_128(qs, wbuf, acc, m0, nbase, g, q2);
        __syncthreads();

        // epilogue: + conv_b + residual, stage as [c][t] f32 in wbuf
        float* outs = (float*)wbuf;  // [128][68] = 34816 B, fits
#pragma unroll
        for (int nt = 0; nt < 8; nt++) {
            int cc = nbase + nt * 8 + q2;
            int t0 = m0 + g, t1 = m0 + 8 + g;
            outs[cc * 68 + t0]       = acc[nt][0] + bias[768 + cc]     + xf[cc * 68 + t0];
            outs[(cc + 1) * 68 + t0] = acc[nt][1] + bias[768 + cc + 1] + xf[(cc + 1) * 68 + t0];
            outs[cc * 68 + t1]       = acc[nt][2] + bias[768 + cc]     + xf[cc * 68 + t1];
            outs[(cc + 1) * 68 + t1] = acc[nt][3] + bias[768 + cc + 1] + xf[(cc + 1) * 68 + t1];
        }
        __syncthreads();

        float* ob = out + (size_t)b * 128 * 262144;
#pragma unroll
        for (int it = 0; it < 8; it++) {
            int idx = it * 256 + tid;
            int c = idx >> 4;
            int row = idx & 15;
            int dd = row >> 2, hh = row & 3;
            *(float4*)(ob + (size_t)c * 262144 + (size_t)(d0 + dd) * 4096 +
                       (h0 + hh) * 64 + w0) = *(float4*)(outs + c * 68 + row * 4);
        }
    }
}

extern "C" void kernel_launch(void* const* d_in, const int* in_sizes, int n_in,
                              void* d_out, int out_size) {
    const float* x      = (const float*)d_in[0];
    const float* ln_g   = (const float*)d_in[1];
    const float* ln_b   = (const float*)d_in[2];
    const float* in_w   = (const float*)d_in[3];
    const float* in_b   = (const float*)d_in[4];
    const float* out_w  = (const float*)d_in[5];
    const float* out_b  = (const float*)d_in[6];
    const float* conv_w = (const float*)d_in[7];
    const float* conv_b = (const float*)d_in[8];
    float* out = (float*)d_out;

    convert_weights_kernel<<<192, 256>>>(in_w, out_w, conv_w);

    cudaFuncSetAttribute(fused_wsa3d_kernel,
                         cudaFuncAttributeMaxDynamicSharedMemorySize, SMEM_BYTES);
    fused_wsa3d_kernel<<<8192, 256, SMEM_BYTES>>>(x, ln_g, ln_b, in_b, out_b,
                                                  conv_b, out);
}

// round 2
// speedup vs baseline: 1.1457x; 1.1457x over previous
#include <cuda_runtime.h>
#include <cuda_bf16.h>
#include <cstdint>

// ---------------------------------------------------------------------------
// WindowedSelfAttention3D fused kernel, v2.
// 512 threads/CTA (16 warps), one window per CTA, 8192 CTAs.
// cp.async double-buffered weight staging; ldmatrix fragment loads.
// ---------------------------------------------------------------------------

#define SMEM_BYTES 178688

#define OFF_XF    0        // float [128][68]   x window (LN input + residual)
#define OFF_ABUF  34816    // bf16  [64][136]   xn -> o
#define OFF_QS    52224    // bf16  [64][136]   q -> y_hi   (outs overlay)
#define OFF_KS    69632    // bf16  [64][136]   k -> y_lo   (outs overlay)
#define OFF_VT    87040    // bf16  [128][72]   v transposed [c][t]
#define OFF_W0    105472   // bf16  [128][136]  weight buf 0
#define OFF_W1    140288   // bf16  [128][136]  weight buf 1
#define OFF_BIAS  175104   // float [896] ln_g,ln_b,in_b,out_b,conv_b

__device__ __align__(16) __nv_bfloat16 g_win[384 * 128];
__device__ __align__(16) __nv_bfloat16 g_wout[128 * 128];
__device__ __align__(16) __nv_bfloat16 g_wc_hi[128 * 128];
__device__ __align__(16) __nv_bfloat16 g_wc_lo[128 * 128];

__global__ void convert_weights_kernel(const float* __restrict__ win,
                                       const float* __restrict__ wout,
                                       const float* __restrict__ wc) {
    int i = blockIdx.x * blockDim.x + threadIdx.x;
    if (i < 384 * 128) g_win[i] = __float2bfloat16(win[i]);
    if (i < 128 * 128) {
        g_wout[i] = __float2bfloat16(wout[i]);
        float f = wc[i];
        __nv_bfloat16 h = __float2bfloat16(f);
        g_wc_hi[i] = h;
        g_wc_lo[i] = __float2bfloat16(f - __bfloat162float(h));
    }
}

__device__ __forceinline__ void mma16816(float acc[4], uint32_t a0, uint32_t a1,
                                         uint32_t a2, uint32_t a3,
                                         uint32_t b0, uint32_t b1) {
    asm volatile(
        "mma.sync.aligned.m16n8k16.row.col.f32.bf16.bf16.f32 "
        "{%0,%1,%2,%3},{%4,%5,%6,%7},{%8,%9},{%0,%1,%2,%3};\n"
        : "+f"(acc[0]), "+f"(acc[1]), "+f"(acc[2]), "+f"(acc[3])
        : "r"(a0), "r"(a1), "r"(a2), "r"(a3), "r"(b0), "r"(b1));
}

__device__ __forceinline__ uint32_t packbf(float lo, float hi) {
    uint32_t r;
    asm("cvt.rn.bf16x2.f32 %0, %1, %2;" : "=r"(r) : "f"(hi), "f"(lo));
    return r;
}

__device__ __forceinline__ void ldsm4(uint32_t& r0, uint32_t& r1, uint32_t& r2,
                                      uint32_t& r3, uint32_t addr) {
    asm volatile("ldmatrix.sync.aligned.m8n8.x4.shared.b16 {%0,%1,%2,%3},[%4];"
                 : "=r"(r0), "=r"(r1), "=r"(r2), "=r"(r3) : "r"(addr));
}

__device__ __forceinline__ uint32_t su32(const void* p) {
    return (uint32_t)__cvta_generic_to_shared(p);
}

#define CPA16(dst, src) \
    asm volatile("cp.async.cg.shared.global [%0],[%1],16;" ::"r"(dst), "l"(src))
#define CPC() asm volatile("cp.async.commit_group;")
#define CPW(n) asm volatile("cp.async.wait_group %0;" ::"n"(n))

// stage 128x128 bf16 row-major weight into smem (stride 136), 4 cp.async/thread
__device__ __forceinline__ void stage_w(const __nv_bfloat16* __restrict__ src,
                                        uint32_t dstu, int tid) {
#pragma unroll
    for (int it = 0; it < 4; it++) {
        int idx = it * 512 + tid;
        int row = idx >> 4, cq = idx & 15;
        CPA16(dstu + row * 272 + cq * 16, src + row * 128 + cq * 8);
    }
}

// D[16][32] += A[16 rows @Au][128] @ W[32 rows @Wu][128]^T, strides 136
__device__ __forceinline__ void gemmv2(uint32_t Au, uint32_t Wu, float acc[4][4]) {
#pragma unroll
    for (int ks = 0; ks < 8; ks++) {
        uint32_t a0, a1, a2, a3, b0, b1, b2, b3, c0, c1, c2, c3;
        ldsm4(a0, a1, a2, a3, Au + ks * 32);
        ldsm4(b0, b1, b2, b3, Wu + ks * 32);
        ldsm4(c0, c1, c2, c3, Wu + 16 * 272 + ks * 32);
        mma16816(acc[0], a0, a1, a2, a3, b0, b2);
        mma16816(acc[1], a0, a1, a2, a3, b1, b3);
        mma16816(acc[2], a0, a1, a2, a3, c0, c2);
        mma16816(acc[3], a0, a1, a2, a3, c1, c3);
    }
}

__global__ void __launch_bounds__(512, 1)
fused_wsa3d_kernel(const float* __restrict__ x,
                   const float* __restrict__ ln_g, const float* __restrict__ ln_b,
                   const float* __restrict__ in_b, const float* __restrict__ out_b,
                   const float* __restrict__ conv_b,
                   float* __restrict__ out) {
    extern __shared__ char sm[];
    float* xf = (float*)(sm + OFF_XF);
    __nv_bfloat16* abuf = (__nv_bfloat16*)(sm + OFF_ABUF);
    __nv_bfloat16* qs = (__nv_bfloat16*)(sm + OFF_QS);
    __nv_bfloat16* ks_ = (__nv_bfloat16*)(sm + OFF_KS);
    __nv_bfloat16* vT = (__nv_bfloat16*)(sm + OFF_VT);
    float* bias = (float*)(sm + OFF_BIAS);

    const int tid = threadIdx.x;
    const int warp = tid >> 5, lane = tid & 31;
    const int g = lane >> 2, q2 = (lane & 3) * 2;
    const int lane16 = lane & 15, laneh = lane >> 4;
    const int mt = warp & 3, ng = warp >> 2;
    const int m0 = mt * 16, nbase = ng * 32;

    const uint32_t s_xf = su32(xf);
    const uint32_t s_abuf = su32(abuf);
    const uint32_t s_qs = su32(qs);
    const uint32_t s_ks = su32(ks_);
    const uint32_t s_vt = su32(vT);
    const uint32_t s_w0 = su32(sm + OFF_W0);
    const uint32_t s_w1 = su32(sm + OFF_W1);

    const uint32_t off136 = (uint32_t)(lane16 * 272 + laneh * 16);
    const uint32_t off72 = (uint32_t)(lane16 * 144 + laneh * 16);

    // window coords
    const int widx = blockIdx.x;
    const int b = widx >> 12;
    const int r3 = widx & 4095;
    const int d0 = (r3 >> 8) * 4;
    const int h0 = ((r3 >> 4) & 15) * 4;
    const int w0 = (r3 & 15) * 4;
    const float* xb = x + (size_t)b * 128 * 262144;

    // ---- issue x window load (cp.async) ----
#pragma unroll
    for (int it = 0; it < 4; it++) {
        int idx = it * 512 + tid;
        int c = idx >> 4, row = idx & 15;
        int dd = row >> 2, hh = row & 3;
        const float* src = xb + (size_t)c * 262144 + (size_t)(d0 + dd) * 4096 +
                           (h0 + hh) * 64 + w0;
        CPA16(s_xf + c * 272 + row * 16, src);
    }
    CPC();
    // ---- issue qkv chunk0 weights ----
    stage_w(g_win, s_w0, tid);
    CPC();
    // biases
    for (int i = tid; i < 896; i += 512) {
        float v;
        if (i < 128)      v = ln_g[i];
        else if (i < 256) v = ln_b[i - 128];
        else if (i < 640) v = in_b[i - 256];
        else if (i < 768) v = out_b[i - 640];
        else              v = conv_b[i - 768];
        bias[i] = v;
    }

    CPW(1);
    __syncthreads();  // xf + bias ready

    // ---- LayerNorm: 8 threads per token ----
    {
        int t = tid >> 3, j = tid & 7;
        float s = 0.f, s2 = 0.f;
#pragma unroll
        for (int i = 0; i < 16; i++) {
            float v = xf[(j + 8 * i) * 68 + t];
            s += v; s2 += v * v;
        }
        s  += __shfl_xor_sync(0xffffffffu, s, 1);
        s  += __shfl_xor_sync(0xffffffffu, s, 2);
        s  += __shfl_xor_sync(0xffffffffu, s, 4);
        s2 += __shfl_xor_sync(0xffffffffu, s2, 1);
        s2 += __shfl_xor_sync(0xffffffffu, s2, 2);
        s2 += __shfl_xor_sync(0xffffffffu, s2, 4);
        float mu = s * (1.f / 128.f);
        float var = s2 * (1.f / 128.f) - mu * mu;
        float rstd = rsqrtf(var + 1e-5f);
#pragma unroll
        for (int i = 0; i < 16; i++) {
            int c = j + 8 * i;
            float v = (xf[c * 68 + t] - mu) * rstd * bias[c] + bias[128 + c];
            abuf[t * 136 + c] = __float2bfloat16(v);
        }
    }

    CPW(0);
    __syncthreads();  // xn + w0 ready

    const uint32_t Aa = s_abuf + m0 * 272 + off136;
    const uint32_t Wn0 = s_w0 + nbase * 272 + off136;
    const uint32_t Wn1 = s_w1 + nbase * 272 + off136;
    const int t0 = m0 + g, t1 = m0 + 8 + g;

    // ---- QKV chunk 0 (q), prefetch chunk 1 ----
    stage_w(g_win + 16384, s_w1, tid);
    CPC();
    {
        float acc[4][4] = {};
        gemmv2(Aa, Wn0, acc);
#pragma unroll
        for (int nt = 0; nt < 4; nt++) {
            int col = nbase + nt * 8 + q2;
            float b0v = bias[256 + col], b1v = bias[256 + col + 1];
            *(uint32_t*)(qs + t0 * 136 + col) = packbf(acc[nt][0] + b0v, acc[nt][1] + b1v);
            *(uint32_t*)(qs + t1 * 136 + col) = packbf(acc[nt][2] + b0v, acc[nt][3] + b1v);
        }
    }
    CPW(0);
    __syncthreads();

    // ---- QKV chunk 1 (k), prefetch chunk 2 ----
    stage_w(g_win + 32768, s_w0, tid);
    CPC();
    {
        float acc[4][4] = {};
        gemmv2(Aa, Wn1, acc);
#pragma unroll
        for (int nt = 0; nt < 4; nt++) {
            int col = nbase + nt * 8 + q2;
            float b0v = bias[384 + col], b1v = bias[384 + col + 1];
            *(uint32_t*)(ks_ + t0 * 136 + col) = packbf(acc[nt][0] + b0v, acc[nt][1] + b1v);
            *(uint32_t*)(ks_ + t1 * 136 + col) = packbf(acc[nt][2] + b0v, acc[nt][3] + b1v);
        }
    }
    CPW(0);
    __syncthreads();

    // ---- QKV chunk 2 (v -> vT), prefetch out_proj W ----
    stage_w(g_wout, s_w1, tid);
    CPC();
    {
        float acc[4][4] = {};
        gemmv2(Aa, Wn0, acc);
#pragma unroll
        for (int nt = 0; nt < 4; nt++) {
            int col = nbase + nt * 8 + q2;
            float b0v = bias[512 + col], b1v = bias[512 + col + 1];
            vT[col * 72 + t0]       = __float2bfloat16(acc[nt][0] + b0v);
            vT[(col + 1) * 72 + t0] = __float2bfloat16(acc[nt][1] + b1v);
            vT[col * 72 + t1]       = __float2bfloat16(acc[nt][2] + b0v);
            vT[(col + 1) * 72 + t1] = __float2bfloat16(acc[nt][3] + b1v);
        }
    }
    CPW(0);
    __syncthreads();

    // ---- Attention: warp = head*4 + mtile ; prefetch conv W_hi ----
    stage_w(g_wc_hi, s_w0, tid);
    CPC();
    {
        const int head = warp >> 2;
        const int m0s = (warp & 3) * 16;
        const uint32_t Aq = s_qs + m0s * 272 + off136 + head * 64;
        const uint32_t Bk = s_ks + off136 + head * 64;

        float P[8][4] = {};
#pragma unroll
        for (int ks2 = 0; ks2 < 2; ks2++) {
            uint32_t a0, a1, a2, a3;
            ldsm4(a0, a1, a2, a3, Aq + ks2 * 32);
#pragma unroll
            for (int p = 0; p < 4; p++) {
                uint32_t b0, b1, b2, b3;
                ldsm4(b0, b1, b2, b3, Bk + p * 4352 + ks2 * 32);
                mma16816(P[2 * p], a0, a1, a2, a3, b0, b2);
                mma16816(P[2 * p + 1], a0, a1, a2, a3, b1, b3);
            }
        }

        const float scale = 0.17677669529663687f;  // 1/sqrt(32)
        float mA = -1e30f, mB = -1e30f;
#pragma unroll
        for (int nt = 0; nt < 8; nt++) {
            mA = fmaxf(mA, fmaxf(P[nt][0], P[nt][1]));
            mB = fmaxf(mB, fmaxf(P[nt][2], P[nt][3]));
        }
        mA = fmaxf(mA, __shfl_xor_sync(0xffffffffu, mA, 1));
        mA = fmaxf(mA, __shfl_xor_sync(0xffffffffu, mA, 2));
        mB = fmaxf(mB, __shfl_xor_sync(0xffffffffu, mB, 1));
        mB = fmaxf(mB, __shfl_xor_sync(0xffffffffu, mB, 2));
        float sA = 0.f, sB = 0.f;
#pragma unroll
        for (int nt = 0; nt < 8; nt++) {
            float e0 = __expf((P[nt][0] - mA) * scale);
            float e1 = __expf((P[nt][1] - mA) * scale);
            float e2 = __expf((P[nt][2] - mB) * scale);
            float e3 = __expf((P[nt][3] - mB) * scale);
            P[nt][0] = e0; P[nt][1] = e1; P[nt][2] = e2; P[nt][3] = e3;
            sA += e0 + e1; sB += e2 + e3;
        }
        sA += __shfl_xor_sync(0xffffffffu, sA, 1);
        sA += __shfl_xor_sync(0xffffffffu, sA, 2);
        sB += __shfl_xor_sync(0xffffffffu, sB, 1);
        sB += __shfl_xor_sync(0xffffffffu, sB, 2);
        float iA = 1.f / sA, iB = 1.f / sB;

        const uint32_t Bv = s_vt + head * 4608 + off72;  // head*32 rows * 144B
        float accO[4][4] = {};
#pragma unroll
        for (int ks = 0; ks < 4; ks++) {
            uint32_t a0 = packbf(P[2 * ks][0] * iA, P[2 * ks][1] * iA);
            uint32_t a1 = packbf(P[2 * ks][2] * iB, P[2 * ks][3] * iB);
            uint32_t a2 = packbf(P[2 * ks + 1][0] * iA, P[2 * ks + 1][1] * iA);
            uint32_t a3 = packbf(P[2 * ks + 1][2] * iB, P[2 * ks + 1][3] * iB);
            uint32_t b0, b1, b2, b3;
            ldsm4(b0, b1, b2, b3, Bv + ks * 32);
            mma16816(accO[0], a0, a1, a2, a3, b0, b2);
            mma16816(accO[1], a0, a1, a2, a3, b1, b3);
            ldsm4(b0, b1, b2, b3, Bv + 16 * 144 + ks * 32);
            mma16816(accO[2], a0, a1, a2, a3, b0, b2);
            mma16816(accO[3], a0, a1, a2, a3, b1, b3);
        }
        // o -> abuf
        int ta = m0s + g, tb = m0s + 8 + g;
#pragma unroll
        for (int nt = 0; nt < 4; nt++) {
            int cc = head * 32 + nt * 8 + q2;
            *(uint32_t*)(abuf + ta * 136 + cc) = packbf(accO[nt][0], accO[nt][1]);
            *(uint32_t*)(abuf + tb * 136 + cc) = packbf(accO[nt][2], accO[nt][3]);
        }
    }
    CPW(0);
    __syncthreads();  // o + W_hi ready

    // ---- out_proj + residual -> y (hi in qs, lo in ks) ----
    {
        float acc[4][4] = {};
        gemmv2(Aa, Wn1, acc);  // W1 = out_proj
#pragma unroll
        for (int nt = 0; nt < 4; nt++) {
            int cc = nbase + nt * 8 + q2;
            float y00 = acc[nt][0] + bias[640 + cc]     + xf[cc * 68 + t0];
            float y01 = acc[nt][1] + bias[640 + cc + 1] + xf[(cc + 1) * 68 + t0];
            float y10 = acc[nt][2] + bias[640 + cc]     + xf[cc * 68 + t1];
            float y11 = acc[nt][3] + bias[640 + cc + 1] + xf[(cc + 1) * 68 + t1];
            float h00 = __bfloat162float(__float2bfloat16(y00));
            float h01 = __bfloat162float(__float2bfloat16(y01));
            float h10 = __bfloat162float(__float2bfloat16(y10));
            float h11 = __bfloat162float(__float2bfloat16(y11));
            *(uint32_t*)(qs + t0 * 136 + cc) = packbf(y00, y01);
            *(uint32_t*)(qs + t1 * 136 + cc) = packbf(y10, y11);
            *(uint32_t*)(ks_ + t0 * 136 + cc) = packbf(y00 - h00, y01 - h01);
            *(uint32_t*)(ks_ + t1 * 136 + cc) = packbf(y10 - h10, y11 - h11);
        }
    }
    __syncthreads();  // y ready, W1 free

    // ---- conv: y_hi@W_hi + y_lo@W_hi + y_hi@W_lo ; prefetch W_lo ----
    stage_w(g_wc_lo, s_w1, tid);
    CPC();
    {
        float acc[4][4] = {};
        const uint32_t Aq = s_qs + m0 * 272 + off136;
        const uint32_t Ak = s_ks + m0 * 272 + off136;
        gemmv2(Aq, Wn0, acc);
        gemmv2(Ak, Wn0, acc);
        CPW(0);
        __syncthreads();  // W_lo ready
        gemmv2(Aq, Wn1, acc);
        __syncthreads();  // all reads of qs done -> outs overlay safe

        float* outs = (float*)(sm + OFF_QS);  // [128][68] f32 overlay
#pragma unroll
        for (int nt = 0; nt < 4; nt++) {
            int cc = nbase + nt * 8 + q2;
            outs[cc * 68 + t0]       = acc[nt][0] + bias[768 + cc]     + xf[cc * 68 + t0];
            outs[(cc + 1) * 68 + t0] = acc[nt][1] + bias[768 + cc + 1] + xf[(cc + 1) * 68 + t0];
            outs[cc * 68 + t1]       = acc[nt][2] + bias[768 + cc]     + xf[cc * 68 + t1];
            outs[(cc + 1) * 68 + t1] = acc[nt][3] + bias[768 + cc + 1] + xf[(cc + 1) * 68 + t1];
        }
        __syncthreads();

        float* ob = out + (size_t)b * 128 * 262144;
#pragma unroll
        for (int it = 0; it < 4; it++) {
            int idx = it * 512 + tid;
            int c = idx >> 4;
            int row = idx & 15;
            int dd = row >> 2, hh = row & 3;
            *(float4*)(ob + (size_t)c * 262144 + (size_t)(d0 + dd) * 4096 +
                       (h0 + hh) * 64 + w0) = *(float4*)(outs + c * 68 + row * 4);
        }
    }
}

extern "C" void kernel_launch(void* const* d_in, const int* in_sizes, int n_in,
                              void* d_out, int out_size) {
    const float* x      = (const float*)d_in[0];
    const float* ln_g   = (const float*)d_in[1];
    const float* ln_b   = (const float*)d_in[2];
    const float* in_w   = (const float*)d_in[3];
    const float* in_b   = (const float*)d_in[4];
    const float* out_w  = (const float*)d_in[5];
    const float* out_b  = (const float*)d_in[6];
    const float* conv_w = (const float*)d_in[7];
    const float* conv_b = (const float*)d_in[8];
    float* out = (float*)d_out;

    convert_weights_kernel<<<192, 256>>>(in_w, out_w, conv_w);

    cudaFuncSetAttribute(fused_wsa3d_kernel,
                         cudaFuncAttributeMaxDynamicSharedMemorySize, SMEM_BYTES);
    fused_wsa3d_kernel<<<8192, 512, SMEM_BYTES>>>(x, ln_g, ln_b, in_b, out_b,
                                                  conv_b, out);
}

// round 3
// speedup vs baseline: 1.3849x; 1.2088x over previous
#include <cuda_runtime.h>
#include <cuda_bf16.h>
#include <cstdint>

// ---------------------------------------------------------------------------
// WindowedSelfAttention3D fused kernel, v3.
// 2 windows per CTA (M=128 GEMMs), 512 threads, 4096 CTAs.
// Single weight buffer with staging overlapped into attention / GEMM phases.
// ---------------------------------------------------------------------------

#define SMEM_BYTES 210432

#define OFF_XF    0        // f32  [128c][132t]  x residual; final out overlay
#define OFF_W     67584    // bf16 [128][136]    weight stage
#define OFF_AB    102400   // bf16 [128][136]    xn -> vT[c][t] -> y_lo
#define OFF_QS    137216   // bf16 [128][136]    q -> o -> y_hi
#define OFF_KS    172032   // bf16 [128][136]    k -> conv_hi weights
#define OFF_BIAS  206848   // f32 [896]

__device__ __align__(16) __nv_bfloat16 g_win[384 * 128];
__device__ __align__(16) __nv_bfloat16 g_wout[128 * 128];
__device__ __align__(16) __nv_bfloat16 g_wc_hi[128 * 128];
__device__ __align__(16) __nv_bfloat16 g_wc_lo[128 * 128];

__global__ void convert_weights_kernel(const float* __restrict__ win,
                                       const float* __restrict__ wout,
                                       const float* __restrict__ wc) {
    int i = blockIdx.x * blockDim.x + threadIdx.x;
    if (i < 384 * 128) g_win[i] = __float2bfloat16(win[i]);
    if (i < 128 * 128) {
        g_wout[i] = __float2bfloat16(wout[i]);
        float f = wc[i];
        __nv_bfloat16 h = __float2bfloat16(f);
        g_wc_hi[i] = h;
        g_wc_lo[i] = __float2bfloat16(f - __bfloat162float(h));
    }
}

__device__ __forceinline__ void mma16816(float acc[4], uint32_t a0, uint32_t a1,
                                         uint32_t a2, uint32_t a3,
                                         uint32_t b0, uint32_t b1) {
    asm volatile(
        "mma.sync.aligned.m16n8k16.row.col.f32.bf16.bf16.f32 "
        "{%0,%1,%2,%3},{%4,%5,%6,%7},{%8,%9},{%0,%1,%2,%3};\n"
        : "+f"(acc[0]), "+f"(acc[1]), "+f"(acc[2]), "+f"(acc[3])
        : "r"(a0), "r"(a1), "r"(a2), "r"(a3), "r"(b0), "r"(b1));
}

__device__ __forceinline__ uint32_t packbf(float lo, float hi) {
    uint32_t r;
    asm("cvt.rn.bf16x2.f32 %0, %1, %2;" : "=r"(r) : "f"(hi), "f"(lo));
    return r;
}

__device__ __forceinline__ void ldsm4(uint32_t& r0, uint32_t& r1, uint32_t& r2,
                                      uint32_t& r3, uint32_t addr) {
    asm volatile("ldmatrix.sync.aligned.m8n8.x4.shared.b16 {%0,%1,%2,%3},[%4];"
                 : "=r"(r0), "=r"(r1), "=r"(r2), "=r"(r3) : "r"(addr));
}

__device__ __forceinline__ uint32_t su32(const void* p) {
    return (uint32_t)__cvta_generic_to_shared(p);
}

#define CPA16(dst, src) \
    asm volatile("cp.async.cg.shared.global [%0],[%1],16;" ::"r"(dst), "l"(src))
#define CPC() asm volatile("cp.async.commit_group;")
#define CPW(n) asm volatile("cp.async.wait_group %0;" ::"n"(n))

// stage 128x128 bf16 row-major block into smem stride 136 (4 cp.async/thread)
__device__ __forceinline__ void stage_w(const __nv_bfloat16* __restrict__ src,
                                        uint32_t dstu, int tid) {
#pragma unroll
    for (int it = 0; it < 4; it++) {
        int idx = it * 512 + tid;
        int row = idx >> 4, cq = idx & 15;
        CPA16(dstu + row * 272 + cq * 16, src + row * 128 + cq * 8);
    }
}

// D[32][32] += A[32 rows @Au][128] @ B[32 rows @Wu][128]^T, row stride 272B
__device__ __forceinline__ void gemm128(uint32_t Au, uint32_t Wu,
                                        float acc[2][4][4]) {
#pragma unroll
    for (int k = 0; k < 8; k++) {
        uint32_t a0, a1, a2, a3, e0, e1, e2, e3;
        uint32_t b0, b1, b2, b3, c0, c1, c2, c3;
        ldsm4(a0, a1, a2, a3, Au + k * 32);
        ldsm4(e0, e1, e2, e3, Au + 4352 + k * 32);
        ldsm4(b0, b1, b2, b3, Wu + k * 32);
        ldsm4(c0, c1, c2, c3, Wu + 4352 + k * 32);
        mma16816(acc[0][0], a0, a1, a2, a3, b0, b2);
        mma16816(acc[0][1], a0, a1, a2, a3, b1, b3);
        mma16816(acc[0][2], a0, a1, a2, a3, c0, c2);
        mma16816(acc[0][3], a0, a1, a2, a3, c1, c3);
        mma16816(acc[1][0], e0, e1, e2, e3, b0, b2);
        mma16816(acc[1][1], e0, e1, e2, e3, b1, b3);
        mma16816(acc[1][2], e0, e1, e2, e3, c0, c2);
        mma16816(acc[1][3], e0, e1, e2, e3, c1, c3);
    }
}

__global__ void __launch_bounds__(512, 1)
fused_wsa3d_kernel(const float* __restrict__ x,
                   const float* __restrict__ ln_g, const float* __restrict__ ln_b,
                   const float* __restrict__ in_b, const float* __restrict__ out_b,
                   const float* __restrict__ conv_b,
                   float* __restrict__ out) {
    extern __shared__ char sm[];
    float* xf = (float*)(sm + OFF_XF);                      // [128c][132t]
    __nv_bfloat16* ab = (__nv_bfloat16*)(sm + OFF_AB);
    __nv_bfloat16* qs = (__nv_bfloat16*)(sm + OFF_QS);
    __nv_bfloat16* ks_ = (__nv_bfloat16*)(sm + OFF_KS);
    float* bias = (float*)(sm + OFF_BIAS);

    const int tid = threadIdx.x;
    const int warp = tid >> 5, lane = tid & 31;
    const int g = lane >> 2, q2 = (lane & 3) * 2;
    const int lane16 = lane & 15, laneh = lane >> 4;
    const int mq = warp & 3, nq = warp >> 2;

    const uint32_t s_xf = su32(xf);
    const uint32_t s_ab = su32(ab);
    const uint32_t s_qs = su32(qs);
    const uint32_t s_ks = su32(ks_);
    const uint32_t s_w = su32(sm + OFF_W);
    const uint32_t off136 = (uint32_t)(lane16 * 272 + laneh * 16);

    // window pair coords
    const int widx = blockIdx.x;
    const int b = widx >> 11;
    const int r = widx & 2047;
    const int d0 = (r >> 7) * 4;
    const int h0 = ((r >> 3) & 15) * 4;
    const int wp = (r & 7) * 8;
    const float* xb = x + (size_t)b * 128 * 262144;

    // ---- x load (2 windows) + qkv0 weights + biases ----
#pragma unroll
    for (int it = 0; it < 8; it++) {
        int idx = it * 512 + tid;
        int c = idx >> 5, rem = idx & 31;
        int win = rem >> 4, row = rem & 15;
        int dd = row >> 2, hh = row & 3;
        CPA16(s_xf + (c * 132 + win * 64 + row * 4) * 4,
              xb + (size_t)c * 262144 + (size_t)(d0 + dd) * 4096 +
                  (h0 + hh) * 64 + wp + win * 4);
    }
    CPC();
    stage_w(g_win, s_w, tid);
    CPC();
    for (int i = tid; i < 896; i += 512) {
        float v;
        if (i < 128)      v = ln_g[i];
        else if (i < 256) v = ln_b[i - 128];
        else if (i < 640) v = in_b[i - 256];
        else if (i < 768) v = out_b[i - 640];
        else              v = conv_b[i - 768];
        bias[i] = v;
    }
    CPW(1);
    __syncthreads();

    // ---- LayerNorm (4 threads / token, 128 tokens) ----
    {
        int t = tid >> 2, j = tid & 3;
        float s = 0.f, s2 = 0.f;
#pragma unroll
        for (int i = 0; i < 32; i++) {
            float v = xf[(j + 4 * i) * 132 + t];
            s += v; s2 += v * v;
        }
        s  += __shfl_xor_sync(0xffffffffu, s, 1);
        s  += __shfl_xor_sync(0xffffffffu, s, 2);
        s2 += __shfl_xor_sync(0xffffffffu, s2, 1);
        s2 += __shfl_xor_sync(0xffffffffu, s2, 2);
        float mu = s * (1.f / 128.f);
        float var = s2 * (1.f / 128.f) - mu * mu;
        float rstd = rsqrtf(var + 1e-5f);
#pragma unroll
        for (int i = 0; i < 32; i++) {
            int c = j + 4 * i;
            float v = (xf[c * 132 + t] - mu) * rstd * bias[c] + bias[128 + c];
            ab[t * 136 + c] = __float2bfloat16(v);
        }
    }
    CPW(0);
    __syncthreads();

    const uint32_t Aab = s_ab + mq * 32 * 272 + off136;
    const uint32_t Aqs = s_qs + mq * 32 * 272 + off136;
    const uint32_t Wn = s_w + nq * 32 * 272 + off136;
    const uint32_t Wk = s_ks + nq * 32 * 272 + off136;

    // ---- Q = xn @ Win0 ----
    {
        float acc[2][4][4] = {};
        gemm128(Aab, Wn, acc);
#pragma unroll
        for (int m = 0; m < 2; m++)
#pragma unroll
            for (int nt = 0; nt < 4; nt++) {
                int cc = nq * 32 + nt * 8 + q2;
                int ra = mq * 32 + m * 16 + g, rb = ra + 8;
                float b0 = bias[256 + cc], b1 = bias[256 + cc + 1];
                *(uint32_t*)(qs + ra * 136 + cc) = packbf(acc[m][nt][0] + b0, acc[m][nt][1] + b1);
                *(uint32_t*)(qs + rb * 136 + cc) = packbf(acc[m][nt][2] + b0, acc[m][nt][3] + b1);
            }
    }
    __syncthreads();
    stage_w(g_win + 16384, s_w, tid);
    CPC(); CPW(0);
    __syncthreads();

    // ---- K = xn @ Win1 ----
    {
        float acc[2][4][4] = {};
        gemm128(Aab, Wn, acc);
#pragma unroll
        for (int m = 0; m < 2; m++)
#pragma unroll
            for (int nt = 0; nt < 4; nt++) {
                int cc = nq * 32 + nt * 8 + q2;
                int ra = mq * 32 + m * 16 + g, rb = ra + 8;
                float b0 = bias[384 + cc], b1 = bias[384 + cc + 1];
                *(uint32_t*)(ks_ + ra * 136 + cc) = packbf(acc[m][nt][0] + b0, acc[m][nt][1] + b1);
                *(uint32_t*)(ks_ + rb * 136 + cc) = packbf(acc[m][nt][2] + b0, acc[m][nt][3] + b1);
            }
    }
    __syncthreads();
    stage_w(g_win + 32768, s_w, tid);
    CPC(); CPW(0);
    __syncthreads();

    // ---- V = xn @ Win2 -> vT[c][t] into ab (after barrier) ----
    {
        float acc[2][4][4] = {};
        gemm128(Aab, Wn, acc);
        __syncthreads();  // all xn reads done before vT overwrite
#pragma unroll
        for (int m = 0; m < 2; m++)
#pragma unroll
            for (int nt = 0; nt < 4; nt++) {
                int cc = nq * 32 + nt * 8 + q2;
                int ra = mq * 32 + m * 16 + g, rb = ra + 8;
                float b0 = bias[512 + cc], b1 = bias[512 + cc + 1];
                ab[cc * 136 + ra]       = __float2bfloat16(acc[m][nt][0] + b0);
                ab[(cc + 1) * 136 + ra] = __float2bfloat16(acc[m][nt][1] + b1);
                ab[cc * 136 + rb]       = __float2bfloat16(acc[m][nt][2] + b0);
                ab[(cc + 1) * 136 + rb] = __float2bfloat16(acc[m][nt][3] + b1);
            }
    }
    stage_w(g_wout, s_w, tid);  // overlaps attention
    CPC();
    __syncthreads();  // vT visible

    // ---- Attention: 32 tasks (win,head,mtile), 2 per warp ----
#pragma unroll 1
    for (int ti = 0; ti < 2; ti++) {
        const int task = warp + ti * 16;
        const int win = task >> 4;
        const int head = (task >> 2) & 3;
        const int mt = task & 3;
        const uint32_t Aq = s_qs + (win * 64 + mt * 16) * 272 + off136 + head * 64;
        const uint32_t Bk = s_ks + (win * 64) * 272 + off136 + head * 64;

        float P[8][4] = {};
#pragma unroll
        for (int k2 = 0; k2 < 2; k2++) {
            uint32_t a0, a1, a2, a3;
            ldsm4(a0, a1, a2, a3, Aq + k2 * 32);
#pragma unroll
            for (int p = 0; p < 4; p++) {
                uint32_t b0, b1, b2, b3;
                ldsm4(b0, b1, b2, b3, Bk + p * 4352 + k2 * 32);
                mma16816(P[2 * p], a0, a1, a2, a3, b0, b2);
                mma16816(P[2 * p + 1], a0, a1, a2, a3, b1, b3);
            }
        }
        const float scale = 0.17677669529663687f;  // 1/sqrt(32)
        float mA = -1e30f, mB = -1e30f;
#pragma unroll
        for (int nt = 0; nt < 8; nt++) {
            mA = fmaxf(mA, fmaxf(P[nt][0], P[nt][1]));
            mB = fmaxf(mB, fmaxf(P[nt][2], P[nt][3]));
        }
        mA = fmaxf(mA, __shfl_xor_sync(0xffffffffu, mA, 1));
        mA = fmaxf(mA, __shfl_xor_sync(0xffffffffu, mA, 2));
        mB = fmaxf(mB, __shfl_xor_sync(0xffffffffu, mB, 1));
        mB = fmaxf(mB, __shfl_xor_sync(0xffffffffu, mB, 2));
        float sA = 0.f, sB = 0.f;
#pragma unroll
        for (int nt = 0; nt < 8; nt++) {
            float e0 = __expf((P[nt][0] - mA) * scale);
            float e1 = __expf((P[nt][1] - mA) * scale);
            float e2 = __expf((P[nt][2] - mB) * scale);
            float e3 = __expf((P[nt][3] - mB) * scale);
            P[nt][0] = e0; P[nt][1] = e1; P[nt][2] = e2; P[nt][3] = e3;
            sA += e0 + e1; sB += e2 + e3;
        }
        sA += __shfl_xor_sync(0xffffffffu, sA, 1);
        sA += __shfl_xor_sync(0xffffffffu, sA, 2);
        sB += __shfl_xor_sync(0xffffffffu, sB, 1);
        sB += __shfl_xor_sync(0xffffffffu, sB, 2);
        float iA = 1.f / sA, iB = 1.f / sB;

        const uint32_t Bv = s_ab + (head * 32) * 272 + off136 + win * 128;
        float accO[4][4] = {};
#pragma unroll
        for (int ks = 0; ks < 4; ks++) {
            uint32_t a0 = packbf(P[2 * ks][0] * iA, P[2 * ks][1] * iA);
            uint32_t a1 = packbf(P[2 * ks][2] * iB, P[2 * ks][3] * iB);
            uint32_t a2 = packbf(P[2 * ks + 1][0] * iA, P[2 * ks + 1][1] * iA);
            uint32_t a3 = packbf(P[2 * ks + 1][2] * iB, P[2 * ks + 1][3] * iB);
            uint32_t b0, b1, b2, b3;
            ldsm4(b0, b1, b2, b3, Bv + ks * 32);
            mma16816(accO[0], a0, a1, a2, a3, b0, b2);
            mma16816(accO[1], a0, a1, a2, a3, b1, b3);
            ldsm4(b0, b1, b2, b3, Bv + 4352 + ks * 32);
            mma16816(accO[2], a0, a1, a2, a3, b0, b2);
            mma16816(accO[3], a0, a1, a2, a3, b1, b3);
        }
        // o -> qs (own task cells only; race-free)
        int ta = win * 64 + mt * 16 + g, tb = ta + 8;
#pragma unroll
        for (int nt = 0; nt < 4; nt++) {
            int cc = head * 32 + nt * 8 + q2;
            *(uint32_t*)(qs + ta * 136 + cc) = packbf(accO[nt][0], accO[nt][1]);
            *(uint32_t*)(qs + tb * 136 + cc) = packbf(accO[nt][2], accO[nt][3]);
        }
    }
    CPW(0);  // wout staged
    __syncthreads();

    // ---- out_proj (+residual) ; conv_hi stages into ks meanwhile ----
    stage_w(g_wc_hi, s_ks, tid);
    CPC();
    {
        float acc[2][4][4] = {};
        gemm128(Aqs, Wn, acc);  // A = o, B = wout
        __syncthreads();        // all o reads done
        stage_w(g_wc_lo, s_w, tid);  // wout dead after the barrier
        CPC();
#pragma unroll
        for (int m = 0; m < 2; m++)
#pragma unroll
            for (int nt = 0; nt < 4; nt++) {
                int cc = nq * 32 + nt * 8 + q2;
                int ra = mq * 32 + m * 16 + g, rb = ra + 8;
                float y00 = acc[m][nt][0] + bias[640 + cc]     + xf[cc * 132 + ra];
                float y01 = acc[m][nt][1] + bias[640 + cc + 1] + xf[(cc + 1) * 132 + ra];
                float y10 = acc[m][nt][2] + bias[640 + cc]     + xf[cc * 132 + rb];
                float y11 = acc[m][nt][3] + bias[640 + cc + 1] + xf[(cc + 1) * 132 + rb];
                float h00 = __bfloat162float(__float2bfloat16(y00));
                float h01 = __bfloat162float(__float2bfloat16(y01));
                float h10 = __bfloat162float(__float2bfloat16(y10));
                float h11 = __bfloat162float(__float2bfloat16(y11));
                *(uint32_t*)(qs + ra * 136 + cc) = packbf(y00, y01);
                *(uint32_t*)(qs + rb * 136 + cc) = packbf(y10, y11);
                *(uint32_t*)(ab + ra * 136 + cc) = packbf(y00 - h00, y01 - h01);
                *(uint32_t*)(ab + rb * 136 + cc) = packbf(y10 - h10, y11 - h11);
            }
    }
    CPW(1);  // conv_hi ready
    __syncthreads();

    // ---- conv: y_hi@Whi + y_lo@Whi + y_hi@Wlo ----
    {
        float acc[2][4][4] = {};
        gemm128(Aqs, Wk, acc);
        gemm128(Aab, Wk, acc);
        CPW(0);  // conv_lo ready
        __syncthreads();
        gemm128(Aqs, Wn, acc);

        // epilogue in place into xf (each thread owns its cells)
#pragma unroll
        for (int m = 0; m < 2; m++)
#pragma unroll
            for (int nt = 0; nt < 4; nt++) {
                int cc = nq * 32 + nt * 8 + q2;
                int ra = mq * 32 + m * 16 + g, rb = ra + 8;
                xf[cc * 132 + ra]       = acc[m][nt][0] + bias[768 + cc]     + xf[cc * 132 + ra];
                xf[(cc + 1) * 132 + ra] = acc[m][nt][1] + bias[768 + cc + 1] + xf[(cc + 1) * 132 + ra];
                xf[cc * 132 + rb]       = acc[m][nt][2] + bias[768 + cc]     + xf[cc * 132 + rb];
                xf[(cc + 1) * 132 + rb] = acc[m][nt][3] + bias[768 + cc + 1] + xf[(cc + 1) * 132 + rb];
            }
    }
    __syncthreads();

    // ---- store ----
    float* ob = out + (size_t)b * 128 * 262144;
#pragma unroll
    for (int it = 0; it < 8; it++) {
        int idx = it * 512 + tid;
        int c = idx >> 5, rem = idx & 31;
        int win = rem >> 4, row = rem & 15;
        int dd = row >> 2, hh = row & 3;
        *(float4*)(ob + (size_t)c * 262144 + (size_t)(d0 + dd) * 4096 +
                   (h0 + hh) * 64 + wp + win * 4) =
            *(float4*)(xf + c * 132 + win * 64 + row * 4);
    }
}

extern "C" void kernel_launch(void* const* d_in, const int* in_sizes, int n_in,
                              void* d_out, int out_size) {
    const float* x      = (const float*)d_in[0];
    const float* ln_g   = (const float*)d_in[1];
    const float* ln_b   = (const float*)d_in[2];
    const float* in_w   = (const float*)d_in[3];
    const float* in_b   = (const float*)d_in[4];
    const float* out_w  = (const float*)d_in[5];
    const float* out_b  = (const float*)d_in[6];
    const float* conv_w = (const float*)d_in[7];
    const float* conv_b = (const float*)d_in[8];
    float* out = (float*)d_out;

    convert_weights_kernel<<<192, 256>>>(in_w, out_w, conv_w);

    cudaFuncSetAttribute(fused_wsa3d_kernel,
                         cudaFuncAttributeMaxDynamicSharedMemorySize, SMEM_BYTES);
    fused_wsa3d_kernel<<<4096, 512, SMEM_BYTES>>>(x, ln_g, ln_b, in_b, out_b,
                                                  conv_b, out);
}

// round 4
// speedup vs baseline: 1.3867x; 1.0013x over previous
#include <cuda_runtime.h>
#include <cuda_bf16.h>
#include <cstdint>

// ---------------------------------------------------------------------------
// WindowedSelfAttention3D fused kernel, v3.
// 2 windows per CTA (M=128 GEMMs), 512 threads, 4096 CTAs.
// Single weight buffer with staging overlapped into attention / GEMM phases.
// ---------------------------------------------------------------------------

#define SMEM_BYTES 210432

#define OFF_XF    0        // f32  [128c][132t]  x residual; final out overlay
#define OFF_W     67584    // bf16 [128][136]    weight stage
#define OFF_AB    102400   // bf16 [128][136]    xn -> vT[c][t] -> y_lo
#define OFF_QS    137216   // bf16 [128][136]    q -> o -> y_hi
#define OFF_KS    172032   // bf16 [128][136]    k -> conv_hi weights
#define OFF_BIAS  206848   // f32 [896]

__device__ __align__(16) __nv_bfloat16 g_win[384 * 128];
__device__ __align__(16) __nv_bfloat16 g_wout[128 * 128];
__device__ __align__(16) __nv_bfloat16 g_wc_hi[128 * 128];
__device__ __align__(16) __nv_bfloat16 g_wc_lo[128 * 128];

__global__ void convert_weights_kernel(const float* __restrict__ win,
                                       const float* __restrict__ wout,
                                       const float* __restrict__ wc) {
    int i = blockIdx.x * blockDim.x + threadIdx.x;
    if (i < 384 * 128) g_win[i] = __float2bfloat16(win[i]);
    if (i < 128 * 128) {
        g_wout[i] = __float2bfloat16(wout[i]);
        float f = wc[i];
        __nv_bfloat16 h = __float2bfloat16(f);
        g_wc_hi[i] = h;
        g_wc_lo[i] = __float2bfloat16(f - __bfloat162float(h));
    }
}

__device__ __forceinline__ void mma16816(float acc[4], uint32_t a0, uint32_t a1,
                                         uint32_t a2, uint32_t a3,
                                         uint32_t b0, uint32_t b1) {
    asm volatile(
        "mma.sync.aligned.m16n8k16.row.col.f32.bf16.bf16.f32 "
        "{%0,%1,%2,%3},{%4,%5,%6,%7},{%8,%9},{%0,%1,%2,%3};\n"
        : "+f"(acc[0]), "+f"(acc[1]), "+f"(acc[2]), "+f"(acc[3])
        : "r"(a0), "r"(a1), "r"(a2), "r"(a3), "r"(b0), "r"(b1));
}

__device__ __forceinline__ uint32_t packbf(float lo, float hi) {
    uint32_t r;
    asm("cvt.rn.bf16x2.f32 %0, %1, %2;" : "=r"(r) : "f"(hi), "f"(lo));
    return r;
}

__device__ __forceinline__ void ldsm4(uint32_t& r0, uint32_t& r1, uint32_t& r2,
                                      uint32_t& r3, uint32_t addr) {
    asm volatile("ldmatrix.sync.aligned.m8n8.x4.shared.b16 {%0,%1,%2,%3},[%4];"
                 : "=r"(r0), "=r"(r1), "=r"(r2), "=r"(r3) : "r"(addr));
}

__device__ __forceinline__ uint32_t su32(const void* p) {
    return (uint32_t)__cvta_generic_to_shared(p);
}

#define CPA16(dst, src) \
    asm volatile("cp.async.cg.shared.global [%0],[%1],16;" ::"r"(dst), "l"(src))
#define CPC() asm volatile("cp.async.commit_group;")
#define CPW(n) asm volatile("cp.async.wait_group %0;" ::"n"(n))

// stage 128x128 bf16 row-major block into smem stride 136 (4 cp.async/thread)
__device__ __forceinline__ void stage_w(const __nv_bfloat16* __restrict__ src,
                                        uint32_t dstu, int tid) {
#pragma unroll
    for (int it = 0; it < 4; it++) {
        int idx = it * 512 + tid;
        int row = idx >> 4, cq = idx & 15;
        CPA16(dstu + row * 272 + cq * 16, src + row * 128 + cq * 8);
    }
}

// D[32][32] += A[32 rows @Au][128] @ B[32 rows @Wu][128]^T, row stride 272B
__device__ __forceinline__ void gemm128(uint32_t Au, uint32_t Wu,
                                        float acc[2][4][4]) {
#pragma unroll
    for (int k = 0; k < 8; k++) {
        uint32_t a0, a1, a2, a3, e0, e1, e2, e3;
        uint32_t b0, b1, b2, b3, c0, c1, c2, c3;
        ldsm4(a0, a1, a2, a3, Au + k * 32);
        ldsm4(e0, e1, e2, e3, Au + 4352 + k * 32);
        ldsm4(b0, b1, b2, b3, Wu + k * 32);
        ldsm4(c0, c1, c2, c3, Wu + 4352 + k * 32);
        mma16816(acc[0][0], a0, a1, a2, a3, b0, b2);
        mma16816(acc[0][1], a0, a1, a2, a3, b1, b3);
        mma16816(acc[0][2], a0, a1, a2, a3, c0, c2);
        mma16816(acc[0][3], a0, a1, a2, a3, c1, c3);
        mma16816(acc[1][0], e0, e1, e2, e3, b0, b2);
        mma16816(acc[1][1], e0, e1, e2, e3, b1, b3);
        mma16816(acc[1][2], e0, e1, e2, e3, c0, c2);
        mma16816(acc[1][3], e0, e1, e2, e3, c1, c3);
    }
}

__global__ void __launch_bounds__(512, 1)
fused_wsa3d_kernel(const float* __restrict__ x,
                   const float* __restrict__ ln_g, const float* __restrict__ ln_b,
                   const float* __restrict__ in_b, const float* __restrict__ out_b,
                   const float* __restrict__ conv_b,
                   float* __restrict__ out) {
    extern __shared__ char sm[];
    float* xf = (float*)(sm + OFF_XF);                      // [128c][132t]
    __nv_bfloat16* ab = (__nv_bfloat16*)(sm + OFF_AB);
    __nv_bfloat16* qs = (__nv_bfloat16*)(sm + OFF_QS);
    __nv_bfloat16* ks_ = (__nv_bfloat16*)(sm + OFF_KS);
    float* bias = (float*)(sm + OFF_BIAS);

    const int tid = threadIdx.x;
    const int warp = tid >> 5, lane = tid & 31;
    const int g = lane >> 2, q2 = (lane & 3) * 2;
    const int lane16 = lane & 15, laneh = lane >> 4;
    const int mq = warp & 3, nq = warp >> 2;

    const uint32_t s_xf = su32(xf);
    const uint32_t s_ab = su32(ab);
    const uint32_t s_qs = su32(qs);
    const uint32_t s_ks = su32(ks_);
    const uint32_t s_w = su32(sm + OFF_W);
    const uint32_t off136 = (uint32_t)(lane16 * 272 + laneh * 16);

    // window pair coords
    const int widx = blockIdx.x;
    const int b = widx >> 11;
    const int r = widx & 2047;
    const int d0 = (r >> 7) * 4;
    const int h0 = ((r >> 3) & 15) * 4;
    const int wp = (r & 7) * 8;
    const float* xb = x + (size_t)b * 128 * 262144;

    // ---- x load (2 windows) + qkv0 weights + biases ----
#pragma unroll
    for (int it = 0; it < 8; it++) {
        int idx = it * 512 + tid;
        int c = idx >> 5, rem = idx & 31;
        int win = rem >> 4, row = rem & 15;
        int dd = row >> 2, hh = row & 3;
        CPA16(s_xf + (c * 132 + win * 64 + row * 4) * 4,
              xb + (size_t)c * 262144 + (size_t)(d0 + dd) * 4096 +
                  (h0 + hh) * 64 + wp + win * 4);
    }
    CPC();
    stage_w(g_win, s_w, tid);
    CPC();
    for (int i = tid; i < 896; i += 512) {
        float v;
        if (i < 128)      v = ln_g[i];
        else if (i < 256) v = ln_b[i - 128];
        else if (i < 640) v = in_b[i - 256];
        else if (i < 768) v = out_b[i - 640];
        else              v = conv_b[i - 768];
        bias[i] = v;
    }
    CPW(1);
    __syncthreads();

    // ---- LayerNorm (4 threads / token, 128 tokens) ----
    {
        int t = tid >> 2, j = tid & 3;
        float s = 0.f, s2 = 0.f;
#pragma unroll
        for (int i = 0; i < 32; i++) {
            float v = xf[(j + 4 * i) * 132 + t];
            s += v; s2 += v * v;
        }
        s  += __shfl_xor_sync(0xffffffffu, s, 1);
        s  += __shfl_xor_sync(0xffffffffu, s, 2);
        s2 += __shfl_xor_sync(0xffffffffu, s2, 1);
        s2 += __shfl_xor_sync(0xffffffffu, s2, 2);
        float mu = s * (1.f / 128.f);
        float var = s2 * (1.f / 128.f) - mu * mu;
        float rstd = rsqrtf(var + 1e-5f);
#pragma unroll
        for (int i = 0; i < 32; i++) {
            int c = j + 4 * i;
            float v = (xf[c * 132 + t] - mu) * rstd * bias[c] + bias[128 + c];
            ab[t * 136 + c] = __float2bfloat16(v);
        }
    }
    CPW(0);
    __syncthreads();

    const uint32_t Aab = s_ab + mq * 32 * 272 + off136;
    const uint32_t Aqs = s_qs + mq * 32 * 272 + off136;
    const uint32_t Wn = s_w + nq * 32 * 272 + off136;
    const uint32_t Wk = s_ks + nq * 32 * 272 + off136;

    // ---- Q = xn @ Win0 ----
    {
        float acc[2][4][4] = {};
        gemm128(Aab, Wn, acc);
#pragma unroll
        for (int m = 0; m < 2; m++)
#pragma unroll
            for (int nt = 0; nt < 4; nt++) {
                int cc = nq * 32 + nt * 8 + q2;
                int ra = mq * 32 + m * 16 + g, rb = ra + 8;
                float b0 = bias[256 + cc], b1 = bias[256 + cc + 1];
                *(uint32_t*)(qs + ra * 136 + cc) = packbf(acc[m][nt][0] + b0, acc[m][nt][1] + b1);
                *(uint32_t*)(qs + rb * 136 + cc) = packbf(acc[m][nt][2] + b0, acc[m][nt][3] + b1);
            }
    }
    __syncthreads();
    stage_w(g_win + 16384, s_w, tid);
    CPC(); CPW(0);
    __syncthreads();

    // ---- K = xn @ Win1 ----
    {
        float acc[2][4][4] = {};
        gemm128(Aab, Wn, acc);
#pragma unroll
        for (int m = 0; m < 2; m++)
#pragma unroll
            for (int nt = 0; nt < 4; nt++) {
                int cc = nq * 32 + nt * 8 + q2;
                int ra = mq * 32 + m * 16 + g, rb = ra + 8;
                float b0 = bias[384 + cc], b1 = bias[384 + cc + 1];
                *(uint32_t*)(ks_ + ra * 136 + cc) = packbf(acc[m][nt][0] + b0, acc[m][nt][1] + b1);
                *(uint32_t*)(ks_ + rb * 136 + cc) = packbf(acc[m][nt][2] + b0, acc[m][nt][3] + b1);
            }
    }
    __syncthreads();
    stage_w(g_win + 32768, s_w, tid);
    CPC(); CPW(0);
    __syncthreads();

    // ---- V = xn @ Win2 -> vT[c][t] into ab (after barrier) ----
    {
        float acc[2][4][4] = {};
        gemm128(Aab, Wn, acc);
        __syncthreads();  // all xn reads done before vT overwrite
#pragma unroll
        for (int m = 0; m < 2; m++)
#pragma unroll
            for (int nt = 0; nt < 4; nt++) {
                int cc = nq * 32 + nt * 8 + q2;
                int ra = mq * 32 + m * 16 + g, rb = ra + 8;
                float b0 = bias[512 + cc], b1 = bias[512 + cc + 1];
                ab[cc * 136 + ra]       = __float2bfloat16(acc[m][nt][0] + b0);
                ab[(cc + 1) * 136 + ra] = __float2bfloat16(acc[m][nt][1] + b1);
                ab[cc * 136 + rb]       = __float2bfloat16(acc[m][nt][2] + b0);
                ab[(cc + 1) * 136 + rb] = __float2bfloat16(acc[m][nt][3] + b1);
            }
    }
    stage_w(g_wout, s_w, tid);  // overlaps attention
    CPC();
    __syncthreads();  // vT visible

    // ---- Attention: 32 tasks (win,head,mtile), 2 per warp ----
#pragma unroll 1
    for (int ti = 0; ti < 2; ti++) {
        const int task = warp + ti * 16;
        const int win = task >> 4;
        const int head = (task >> 2) & 3;
        const int mt = task & 3;
        const uint32_t Aq = s_qs + (win * 64 + mt * 16) * 272 + off136 + head * 64;
        const uint32_t Bk = s_ks + (win * 64) * 272 + off136 + head * 64;

        float P[8][4] = {};
#pragma unroll
        for (int k2 = 0; k2 < 2; k2++) {
            uint32_t a0, a1, a2, a3;
            ldsm4(a0, a1, a2, a3, Aq + k2 * 32);
#pragma unroll
            for (int p = 0; p < 4; p++) {
                uint32_t b0, b1, b2, b3;
                ldsm4(b0, b1, b2, b3, Bk + p * 4352 + k2 * 32);
                mma16816(P[2 * p], a0, a1, a2, a3, b0, b2);
                mma16816(P[2 * p + 1], a0, a1, a2, a3, b1, b3);
            }
        }
        const float scale = 0.17677669529663687f;  // 1/sqrt(32)
        float mA = -1e30f, mB = -1e30f;
#pragma unroll
        for (int nt = 0; nt < 8; nt++) {
            mA = fmaxf(mA, fmaxf(P[nt][0], P[nt][1]));
            mB = fmaxf(mB, fmaxf(P[nt][2], P[nt][3]));
        }
        mA = fmaxf(mA, __shfl_xor_sync(0xffffffffu, mA, 1));
        mA = fmaxf(mA, __shfl_xor_sync(0xffffffffu, mA, 2));
        mB = fmaxf(mB, __shfl_xor_sync(0xffffffffu, mB, 1));
        mB = fmaxf(mB, __shfl_xor_sync(0xffffffffu, mB, 2));
        float sA = 0.f, sB = 0.f;
#pragma unroll
        for (int nt = 0; nt < 8; nt++) {
            float e0 = __expf((P[nt][0] - mA) * scale);
            float e1 = __expf((P[nt][1] - mA) * scale);
            float e2 = __expf((P[nt][2] - mB) * scale);
            float e3 = __expf((P[nt][3] - mB) * scale);
            P[nt][0] = e0; P[nt][1] = e1; P[nt][2] = e2; P[nt][3] = e3;
            sA += e0 + e1; sB += e2 + e3;
        }
        sA += __shfl_xor_sync(0xffffffffu, sA, 1);
        sA += __shfl_xor_sync(0xffffffffu, sA, 2);
        sB += __shfl_xor_sync(0xffffffffu, sB, 1);
        sB += __shfl_xor_sync(0xffffffffu, sB, 2);
        float iA = 1.f / sA, iB = 1.f / sB;

        const uint32_t Bv = s_ab + (head * 32) * 272 + off136 + win * 128;
        float accO[4][4] = {};
#pragma unroll
        for (int ks = 0; ks < 4; ks++) {
            uint32_t a0 = packbf(P[2 * ks][0] * iA, P[2 * ks][1] * iA);
            uint32_t a1 = packbf(P[2 * ks][2] * iB, P[2 * ks][3] * iB);
            uint32_t a2 = packbf(P[2 * ks + 1][0] * iA, P[2 * ks + 1][1] * iA);
            uint32_t a3 = packbf(P[2 * ks + 1][2] * iB, P[2 * ks + 1][3] * iB);
            uint32_t b0, b1, b2, b3;
            ldsm4(b0, b1, b2, b3, Bv + ks * 32);
            mma16816(accO[0], a0, a1, a2, a3, b0, b2);
            mma16816(accO[1], a0, a1, a2, a3, b1, b3);
            ldsm4(b0, b1, b2, b3, Bv + 4352 + ks * 32);
            mma16816(accO[2], a0, a1, a2, a3, b0, b2);
            mma16816(accO[3], a0, a1, a2, a3, b1, b3);
        }
        // o -> qs (own task cells only; race-free)
        int ta = win * 64 + mt * 16 + g, tb = ta + 8;
#pragma unroll
        for (int nt = 0; nt < 4; nt++) {
            int cc = head * 32 + nt * 8 + q2;
            *(uint32_t*)(qs + ta * 136 + cc) = packbf(accO[nt][0], accO[nt][1]);
            *(uint32_t*)(qs + tb * 136 + cc) = packbf(accO[nt][2], accO[nt][3]);
        }
    }
    CPW(0);  // wout staged
    __syncthreads();

    // ---- out_proj (+residual) ; conv_hi stages into ks meanwhile ----
    stage_w(g_wc_hi, s_ks, tid);
    CPC();
    {
        float acc[2][4][4] = {};
        gemm128(Aqs, Wn, acc);  // A = o, B = wout
        __syncthreads();        // all o reads done
        stage_w(g_wc_lo, s_w, tid);  // wout dead after the barrier
        CPC();
#pragma unroll
        for (int m = 0; m < 2; m++)
#pragma unroll
            for (int nt = 0; nt < 4; nt++) {
                int cc = nq * 32 + nt * 8 + q2;
                int ra = mq * 32 + m * 16 + g, rb = ra + 8;
                float y00 = acc[m][nt][0] + bias[640 + cc]     + xf[cc * 132 + ra];
                float y01 = acc[m][nt][1] + bias[640 + cc + 1] + xf[(cc + 1) * 132 + ra];
                float y10 = acc[m][nt][2] + bias[640 + cc]     + xf[cc * 132 + rb];
                float y11 = acc[m][nt][3] + bias[640 + cc + 1] + xf[(cc + 1) * 132 + rb];
                float h00 = __bfloat162float(__float2bfloat16(y00));
                float h01 = __bfloat162float(__float2bfloat16(y01));
                float h10 = __bfloat162float(__float2bfloat16(y10));
                float h11 = __bfloat162float(__float2bfloat16(y11));
                *(uint32_t*)(qs + ra * 136 + cc) = packbf(y00, y01);
                *(uint32_t*)(qs + rb * 136 + cc) = packbf(y10, y11);
                *(uint32_t*)(ab + ra * 136 + cc) = packbf(y00 - h00, y01 - h01);
                *(uint32_t*)(ab + rb * 136 + cc) = packbf(y10 - h10, y11 - h11);
            }
    }
    CPW(1);  // conv_hi ready
    __syncthreads();

    // ---- conv: y_hi@Whi + y_lo@Whi + y_hi@Wlo ----
    {
        float acc[2][4][4] = {};
        gemm128(Aqs, Wk, acc);
        gemm128(Aab, Wk, acc);
        CPW(0);  // conv_lo ready
        __syncthreads();
        gemm128(Aqs, Wn, acc);

        // epilogue in place into xf (each thread owns its cells)
#pragma unroll
        for (int m = 0; m < 2; m++)
#pragma unroll
            for (int nt = 0; nt < 4; nt++) {
                int cc = nq * 32 + nt * 8 + q2;
                int ra = mq * 32 + m * 16 + g, rb = ra + 8;
                xf[cc * 132 + ra]       = acc[m][nt][0] + bias[768 + cc]     + xf[cc * 132 + ra];
                xf[(cc + 1) * 132 + ra] = acc[m][nt][1] + bias[768 + cc + 1] + xf[(cc + 1) * 132 + ra];
                xf[cc * 132 + rb]       = acc[m][nt][2] + bias[768 + cc]     + xf[cc * 132 + rb];
                xf[(cc + 1) * 132 + rb] = acc[m][nt][3] + bias[768 + cc + 1] + xf[(cc + 1) * 132 + rb];
            }
    }
    __syncthreads();

    // ---- store ----
    float* ob = out + (size_t)b * 128 * 262144;
#pragma unroll
    for (int it = 0; it < 8; it++) {
        int idx = it * 512 + tid;
        int c = idx >> 5, rem = idx & 31;
        int win = rem >> 4, row = rem & 15;
        int dd = row >> 2, hh = row & 3;
        *(float4*)(ob + (size_t)c * 262144 + (size_t)(d0 + dd) * 4096 +
                   (h0 + hh) * 64 + wp + win * 4) =
            *(float4*)(xf + c * 132 + win * 64 + row * 4);
    }
}

extern "C" void kernel_launch(void* const* d_in, const int* in_sizes, int n_in,
                              void* d_out, int out_size) {
    const float* x      = (const float*)d_in[0];
    const float* ln_g   = (const float*)d_in[1];
    const float* ln_b   = (const float*)d_in[2];
    const float* in_w   = (const float*)d_in[3];
    const float* in_b   = (const float*)d_in[4];
    const float* out_w  = (const float*)d_in[5];
    const float* out_b  = (const float*)d_in[6];
    const float* conv_w = (const float*)d_in[7];
    const float* conv_b = (const float*)d_in[8];
    float* out = (float*)d_out;

    convert_weights_kernel<<<192, 256>>>(in_w, out_w, conv_w);

    cudaFuncSetAttribute(fused_wsa3d_kernel,
                         cudaFuncAttributeMaxDynamicSharedMemorySize, SMEM_BYTES);
    fused_wsa3d_kernel<<<4096, 512, SMEM_BYTES>>>(x, ln_g, ln_b, in_b, out_b,
                                                  conv_b, out);
}